// round 15
// baseline (speedup 1.0000x reference)
#include <cuda_runtime.h>
#include <cuda_bf16.h>
#include <cuda_fp16.h>
#include <cstdint>

#define N_NODES 50000
#define E_EDGES 800000
#define SCAN_B 512

// ---------------- device scratch (static, no allocation) ----------------
__device__ float g_q[N_NODES * 128];
__device__ float g_skip[N_NODES * 32];
__device__ __align__(16) __half g_kvh[N_NODES * 256];  // [node]: k ch0-127, v ch128-255
__device__ int   g_deg[N_NODES];
__device__ int   g_cnt[N_NODES];
__device__ int   g_off[N_NODES];
__device__ int   g_bsum[(N_NODES + SCAN_B - 1) / SCAN_B + 1];
__device__ int   g_srcs[E_EDGES];
// bf16 hi/lo of x (padded to full 128-row tiles; pad stays zero) and W^T per y
__device__ __align__(16) __nv_bfloat16 g_ah[(N_NODES + 128) * 256];
__device__ __align__(16) __nv_bfloat16 g_al[(N_NODES + 128) * 256];
__device__ __align__(16) __nv_bfloat16 g_bh[4 * 128 * 256];
__device__ __align__(16) __nv_bfloat16 g_bl[4 * 128 * 256];

// ---------------- helpers ----------------
__device__ __forceinline__ uint32_t smem_u32(const void* p) {
    uint32_t a;
    asm("{ .reg .u64 t; cvta.to.shared.u64 t, %1; cvt.u32.u64 %0, t; }" : "=r"(a) : "l"(p));
    return a;
}
// SW64 swizzle for 64-byte rows: XOR bits [5:4] with bits [8:7]
#define SWZ64(b) ((b) ^ (((b) >> 3) & 0x30))

__device__ __forceinline__ uint32_t pack_bf16(float a, float b) {
    __nv_bfloat162 h = __floats2bfloat162_rn(a, b);
    return *(uint32_t*)&h;
}

__device__ __forceinline__ void ldsm_x4(uint32_t* r, uint32_t addr) {
    asm volatile("ldmatrix.sync.aligned.m8n8.x4.shared.b16 {%0,%1,%2,%3}, [%4];"
                 : "=r"(r[0]), "=r"(r[1]), "=r"(r[2]), "=r"(r[3]) : "r"(addr));
}

__device__ __forceinline__ void mma16816(float* d, const uint32_t* a, const uint32_t* b) {
    asm volatile(
        "mma.sync.aligned.m16n8k16.row.col.f32.bf16.bf16.f32 "
        "{%0,%1,%2,%3}, {%4,%5,%6,%7}, {%8,%9}, {%0,%1,%2,%3};"
        : "+f"(d[0]), "+f"(d[1]), "+f"(d[2]), "+f"(d[3])
        : "r"(a[0]), "r"(a[1]), "r"(a[2]), "r"(a[3]), "r"(b[0]), "r"(b[1]));
}

// ---------------- conversion kernels ----------------
__global__ void convA_kernel(const float* __restrict__ x, int total4) {
    int i = blockIdx.x * blockDim.x + threadIdx.x;
    if (i >= total4) return;
    float4 v = ((const float4*)x)[i];
    float h0 = __bfloat162float(__float2bfloat16(v.x));
    float h1 = __bfloat162float(__float2bfloat16(v.y));
    float h2 = __bfloat162float(__float2bfloat16(v.z));
    float h3 = __bfloat162float(__float2bfloat16(v.w));
    ((uint2*)g_ah)[i] = make_uint2(pack_bf16(v.x, v.y), pack_bf16(v.z, v.w));
    ((uint2*)g_al)[i] = make_uint2(pack_bf16(v.x - h0, v.y - h1), pack_bf16(v.z - h2, v.w - h3));
}

__global__ void convW_kernel(
    const float* __restrict__ Wq, const float* __restrict__ Wk,
    const float* __restrict__ Wv, const float* __restrict__ Ws)
{
    int y = blockIdx.y;
    const float* W = (y == 0) ? Wq : (y == 1) ? Wk : (y == 2) ? Wv : Ws;
    int N = (y == 3) ? 32 : 128;
    int idx = blockIdx.x * blockDim.x + threadIdx.x;
    if (idx >= 256 * N) return;
    int k = idx / N, nn = idx % N;
    float w = W[idx];
    float h = __bfloat162float(__float2bfloat16(w));
    size_t o = (size_t)y * 32768 + (size_t)nn * 256 + k;  // transposed [n][k]
    g_bh[o] = __float2bfloat16(w);
    g_bl[o] = __float2bfloat16(w - h);
}

// ---------------- init / CSR build ----------------
__global__ void init_kernel(int n) {
    int i = blockIdx.x * blockDim.x + threadIdx.x;
    if (i < n) { g_deg[i] = 0; g_cnt[i] = 0; }
}
__global__ void degree_kernel(const int* __restrict__ ei, int E) {
    int i = blockIdx.x * blockDim.x + threadIdx.x;
    if (i < E) atomicAdd(&g_deg[ei[(size_t)E + i]], 1);
}
__global__ void scan1_kernel(int n) {
    __shared__ int sm[SCAN_B];
    int i = blockIdx.x * SCAN_B + threadIdx.x;
    int v = (i < n) ? g_deg[i] : 0;
    sm[threadIdx.x] = v;
    __syncthreads();
#pragma unroll
    for (int ofs = 1; ofs < SCAN_B; ofs <<= 1) {
        int t = (threadIdx.x >= ofs) ? sm[threadIdx.x - ofs] : 0;
        __syncthreads();
        sm[threadIdx.x] += t;
        __syncthreads();
    }
    if (i < n) g_off[i] = sm[threadIdx.x] - v;
    if (threadIdx.x == SCAN_B - 1) g_bsum[blockIdx.x] = sm[SCAN_B - 1];
}
__global__ void scan2_kernel(int nb) {
    __shared__ int sm[128];
    int v = ((int)threadIdx.x < nb) ? g_bsum[threadIdx.x] : 0;
    sm[threadIdx.x] = v;
    __syncthreads();
#pragma unroll
    for (int ofs = 1; ofs < 128; ofs <<= 1) {
        int t = (threadIdx.x >= ofs) ? sm[threadIdx.x - ofs] : 0;
        __syncthreads();
        sm[threadIdx.x] += t;
        __syncthreads();
    }
    if ((int)threadIdx.x < nb) g_bsum[threadIdx.x] = sm[threadIdx.x] - v;
}
__global__ void fill_kernel(const int* __restrict__ ei, int E) {
    int i = blockIdx.x * blockDim.x + threadIdx.x;
    if (i >= E) return;
    int src = ei[i];
    int dst = ei[(size_t)E + i];
    int pos = g_off[dst] + g_bsum[dst / SCAN_B] + atomicAdd(&g_cnt[dst], 1);
    g_srcs[pos] = src;
}

// ---------------- fused mma.sync GEMM: K-chunks of 32, 32KB smem -------------
// q (y=0), skip (y=3): 3 passes (AhBh + AlBh + AhBl), frags loaded ONCE/k-step.
// k (y=1), v (y=2): 1 pass (AhBh) — x-lo and W-lo corrections dropped (err
// budget: ~sqrt(2) x measured 4.1e-4 = ~5.8e-4 < 1e-3 gate).
#define SM_AH   0
#define SM_AL   8192
#define SM_BH   16384
#define SM_BL   24576
#define SM_TOTAL 32768

__global__ void __launch_bounds__(256) gemm_mma_kernel(
    const float* __restrict__ bq, const float* __restrict__ bk,
    const float* __restrict__ bv, const float* __restrict__ bs,
    int M)
{
    extern __shared__ char smem[];
    uint32_t sb = smem_u32(smem);
    int t = threadIdx.x;
    int wid = t >> 5, lane = t & 31;
    int y = blockIdx.y;

    const float* bias = (y == 0) ? bq : (y == 1) ? bk : (y == 2) ? bv : bs;
    float* C = (y == 0) ? g_q : g_skip;  // y=1,2 write g_kvh (half)
    int N = (y == 3) ? 32 : 128;
    bool three = (y == 0 || y == 3);     // 3-pass split; k/v single-pass

    const __nv_bfloat16* Bh = g_bh + (size_t)y * 32768;
    const __nv_bfloat16* Bl = g_bl + (size_t)y * 32768;

    int wr = wid >> 1;
    int wc = wid & 1;
    int rowBase = blockIdx.x * 128;

    int npairs = (N - wc * 64) / 16;
    if (npairs < 0) npairs = 0;
    if (npairs > 4) npairs = 4;

    float acc[2][8][4];
#pragma unroll
    for (int i = 0; i < 2; i++)
#pragma unroll
        for (int j = 0; j < 8; j++)
#pragma unroll
            for (int q = 0; q < 4; q++) acc[i][j][q] = 0.0f;

    int a_row = lane & 15;
    int a_k   = (lane >> 4) * 8;
    int b_n   = ((lane >> 4) << 3) + (lane & 7);
    int b_k   = lane & 8;

    for (int c = 0; c < 8; c++) {
        // tile fill: 8KB per matrix = 512 16B segs; 2 segs/thread/matrix.
#pragma unroll
        for (int jj = 0; jj < 2; jj++) {
            int id = t * 2 + jj;           // 0..511
            int row = id >> 2;             // 0..127
            int seg = id & 3;              // 16B segment within 64B row
            uint32_t so = SWZ64((uint32_t)(row * 64 + seg * 16));
            size_t ga = (size_t)(rowBase + row) * 256 + c * 32 + seg * 8;
            size_t gb = (size_t)row * 256 + c * 32 + seg * 8;
            *(uint4*)(smem + SM_AH + so) = *(const uint4*)(g_ah + ga);
            *(uint4*)(smem + SM_BH + so) = *(const uint4*)(Bh + gb);
            if (three) {
                *(uint4*)(smem + SM_AL + so) = *(const uint4*)(g_al + ga);
                *(uint4*)(smem + SM_BL + so) = *(const uint4*)(Bl + gb);
            }
        }
        __syncthreads();

#pragma unroll
        for (int ks = 0; ks < 2; ks++) {
            int k0 = ks * 16;
            // load ALL fragments for this k-step once
            uint32_t ah[2][4], al[2][4];
#pragma unroll
            for (int mt = 0; mt < 2; mt++) {
                int rr = wr * 32 + mt * 16 + a_row;
                uint32_t off = SWZ64((uint32_t)(rr * 64 + (k0 + a_k) * 2));
                ldsm_x4(ah[mt], sb + SM_AH + off);
                if (three) ldsm_x4(al[mt], sb + SM_AL + off);
            }
            uint32_t bh[4][4], bl[4][4];
            for (int j = 0; j < npairs; j++) {
                int nn = wc * 64 + j * 16 + b_n;
                uint32_t off = SWZ64((uint32_t)(nn * 64 + (k0 + b_k) * 2));
                ldsm_x4(bh[j], sb + SM_BH + off);
                if (three) ldsm_x4(bl[j], sb + SM_BL + off);
            }
            // pass hh
#pragma unroll
            for (int mt = 0; mt < 2; mt++)
                for (int j = 0; j < npairs; j++) {
                    mma16816(acc[mt][2 * j + 0], ah[mt], &bh[j][0]);
                    mma16816(acc[mt][2 * j + 1], ah[mt], &bh[j][2]);
                }
            if (three) {
                // pass lh
#pragma unroll
                for (int mt = 0; mt < 2; mt++)
                    for (int j = 0; j < npairs; j++) {
                        mma16816(acc[mt][2 * j + 0], al[mt], &bh[j][0]);
                        mma16816(acc[mt][2 * j + 1], al[mt], &bh[j][2]);
                    }
                // pass hl
#pragma unroll
                for (int mt = 0; mt < 2; mt++)
                    for (int j = 0; j < npairs; j++) {
                        mma16816(acc[mt][2 * j + 0], ah[mt], &bl[j][0]);
                        mma16816(acc[mt][2 * j + 1], ah[mt], &bl[j][2]);
                    }
            }
        }
        __syncthreads();
    }

    // epilogue: q/skip -> fp32, k/v -> half into g_kvh
#pragma unroll
    for (int mt = 0; mt < 2; mt++) {
        for (int nt = 0; nt < npairs * 2; nt++) {
            int col = wc * 64 + nt * 8 + 2 * (lane & 3);
            int rr0 = rowBase + wr * 32 + mt * 16 + (lane >> 2);
            int rr1 = rr0 + 8;
            float bx = bias[col], by = bias[col + 1];
            float o00 = acc[mt][nt][0] + bx, o01 = acc[mt][nt][1] + by;
            float o10 = acc[mt][nt][2] + bx, o11 = acc[mt][nt][3] + by;
            if (three) {
                if (rr0 < M) *(float2*)&C[(size_t)rr0 * N + col] = make_float2(o00, o01);
                if (rr1 < M) *(float2*)&C[(size_t)rr1 * N + col] = make_float2(o10, o11);
            } else {
                int off = (y == 1) ? 0 : 128;
                if (rr0 < M) *(__half2*)&g_kvh[(size_t)rr0 * 256 + off + col] = __floats2half2_rn(o00, o01);
                if (rr1 < M) *(__half2*)&g_kvh[(size_t)rr1 * 256 + off + col] = __floats2half2_rn(o10, o11);
            }
        }
    }
}

// ---------------- fused aggregation: warp per dst, 2-edge ILP (R9/R11 best) -
__global__ void __launch_bounds__(256) aggregate_kernel(float* __restrict__ out, int n) {
    int w = (int)((blockIdx.x * 256u + threadIdx.x) >> 5);
    if (w >= n) return;
    int lane = threadIdx.x & 31;

    int start = g_off[w] + g_bsum[w / SCAN_B];
    int deg = g_deg[w];
    int end = start + deg;

    float4 q4 = *(const float4*)(g_q + (size_t)w * 128 + lane * 4);
    float4 num = make_float4(0.f, 0.f, 0.f, 0.f);
    float den = 0.0f;
    const float scale = 0.17677669529663687f;  // 1/sqrt(32)

    for (int base = start; base < end; base += 32) {
        int m = end - base;
        int cntc = (m < 32) ? m : 32;
        int my = (lane < cntc) ? g_srcs[base + lane] : 0;
        int i = 0;
        for (; i + 2 <= cntc; i += 2) {
            int s0 = __shfl_sync(0xffffffffu, my, i);
            int s1 = __shfl_sync(0xffffffffu, my, i + 1);
            uint2 kr0 = *(const uint2*)(g_kvh + (size_t)s0 * 256 + lane * 4);
            uint2 kr1 = *(const uint2*)(g_kvh + (size_t)s1 * 256 + lane * 4);
            uint2 vr0 = *(const uint2*)(g_kvh + (size_t)s0 * 256 + 128 + lane * 4);
            uint2 vr1 = *(const uint2*)(g_kvh + (size_t)s1 * 256 + 128 + lane * 4);
            float2 k0a = __half22float2(*(__half2*)&kr0.x), k0b = __half22float2(*(__half2*)&kr0.y);
            float2 k1a = __half22float2(*(__half2*)&kr1.x), k1b = __half22float2(*(__half2*)&kr1.y);
            float p0 = q4.x * k0a.x + q4.y * k0a.y + q4.z * k0b.x + q4.w * k0b.y;
            float p1 = q4.x * k1a.x + q4.y * k1a.y + q4.z * k1b.x + q4.w * k1b.y;
            p0 += __shfl_xor_sync(0xffffffffu, p0, 1);
            p1 += __shfl_xor_sync(0xffffffffu, p1, 1);
            p0 += __shfl_xor_sync(0xffffffffu, p0, 2);
            p1 += __shfl_xor_sync(0xffffffffu, p1, 2);
            p0 += __shfl_xor_sync(0xffffffffu, p0, 4);
            p1 += __shfl_xor_sync(0xffffffffu, p1, 4);
            float e0 = __expf(p0 * scale);
            float e1 = __expf(p1 * scale);
            den += e0 + e1;
            float2 v0a = __half22float2(*(__half2*)&vr0.x), v0b = __half22float2(*(__half2*)&vr0.y);
            float2 v1a = __half22float2(*(__half2*)&vr1.x), v1b = __half22float2(*(__half2*)&vr1.y);
            num.x = fmaf(e0, v0a.x, fmaf(e1, v1a.x, num.x));
            num.y = fmaf(e0, v0a.y, fmaf(e1, v1a.y, num.y));
            num.z = fmaf(e0, v0b.x, fmaf(e1, v1b.x, num.z));
            num.w = fmaf(e0, v0b.y, fmaf(e1, v1b.y, num.w));
        }
        if (i < cntc) {
            int s0 = __shfl_sync(0xffffffffu, my, i);
            uint2 kr0 = *(const uint2*)(g_kvh + (size_t)s0 * 256 + lane * 4);
            uint2 vr0 = *(const uint2*)(g_kvh + (size_t)s0 * 256 + 128 + lane * 4);
            float2 k0a = __half22float2(*(__half2*)&kr0.x), k0b = __half22float2(*(__half2*)&kr0.y);
            float p0 = q4.x * k0a.x + q4.y * k0a.y + q4.z * k0b.x + q4.w * k0b.y;
            p0 += __shfl_xor_sync(0xffffffffu, p0, 1);
            p0 += __shfl_xor_sync(0xffffffffu, p0, 2);
            p0 += __shfl_xor_sync(0xffffffffu, p0, 4);
            float e0 = __expf(p0 * scale);
            den += e0;
            float2 v0a = __half22float2(*(__half2*)&vr0.x), v0b = __half22float2(*(__half2*)&vr0.y);
            num.x = fmaf(e0, v0a.x, num.x);
            num.y = fmaf(e0, v0a.y, num.y);
            num.z = fmaf(e0, v0b.x, num.z);
            num.w = fmaf(e0, v0b.y, num.w);
        }
    }

    float inv = (deg > 0) ? (1.0f / den) : 0.0f;
    num.x *= inv; num.y *= inv; num.z *= inv; num.w *= inv;

#pragma unroll
    for (int ofs = 8; ofs <= 16; ofs <<= 1) {
        num.x += __shfl_xor_sync(0xffffffffu, num.x, ofs);
        num.y += __shfl_xor_sync(0xffffffffu, num.y, ofs);
        num.z += __shfl_xor_sync(0xffffffffu, num.z, ofs);
        num.w += __shfl_xor_sync(0xffffffffu, num.w, ofs);
    }

    if (lane < 8) {
        float4 sk = *(const float4*)(g_skip + (size_t)w * 32 + lane * 4);
        float4 o;
        o.x = 0.25f * num.x + sk.x;
        o.y = 0.25f * num.y + sk.y;
        o.z = 0.25f * num.z + sk.z;
        o.w = 0.25f * num.w + sk.w;
        o.x = (o.x > 0.f) ? o.x : 0.1f * o.x;
        o.y = (o.y > 0.f) ? o.y : 0.1f * o.y;
        o.z = (o.z > 0.f) ? o.z : 0.1f * o.z;
        o.w = (o.w > 0.f) ? o.w : 0.1f * o.w;
        *(float4*)(out + (size_t)w * 32 + lane * 4) = o;
    }
}

// ---------------- launch ----------------
// Submission order puts the fused GEMM at slot #4 (ncu profiles launch #4).
extern "C" void kernel_launch(void* const* d_in, const int* in_sizes, int n_in,
                              void* d_out, int out_size) {
    const float* x  = (const float*)d_in[0];
    const int*   ei = (const int*)d_in[1];
    const float* Wq = (const float*)d_in[2];
    const float* bq = (const float*)d_in[3];
    const float* Wk = (const float*)d_in[4];
    const float* bk = (const float*)d_in[5];
    const float* Wv = (const float*)d_in[6];
    const float* bv = (const float*)d_in[7];
    const float* Ws = (const float*)d_in[8];
    const float* bs = (const float*)d_in[9];
    float* out = (float*)d_out;

    int n = in_sizes[0] / 256;   // 50000
    int E = in_sizes[1] / 2;     // 800000
    int nb = (n + SCAN_B - 1) / SCAN_B;

    static cudaStream_t s1 = nullptr;
    static cudaEvent_t evFork = nullptr, evJoin = nullptr;
    if (s1 == nullptr) {
        cudaStreamCreateWithFlags(&s1, cudaStreamNonBlocking);
        cudaEventCreateWithFlags(&evFork, cudaEventDisableTiming);
        cudaEventCreateWithFlags(&evJoin, cudaEventDisableTiming);
        cudaFuncSetAttribute(gemm_mma_kernel,
                             cudaFuncAttributeMaxDynamicSharedMemorySize, SM_TOTAL);
    }

    // fork for s1 (events are not launches)
    cudaEventRecord(evFork, 0);
    cudaStreamWaitEvent(s1, evFork, 0);

    // launches #1-2: conversions (main)
    convA_kernel<<<(n * 64 + 255) / 256, 256>>>(x, n * 64);
    {
        dim3 wgrid((256 * 128 + 255) / 256, 4);
        convW_kernel<<<wgrid, 256>>>(Wq, Wk, Wv, Ws);
    }
    // launch #3: CSR init (s1)
    init_kernel<<<(n + 255) / 256, 256, 0, s1>>>(n);
    // launch #4: fused GEMM (main) <- ncu window
    dim3 ggrid((n + 127) / 128, 4);
    gemm_mma_kernel<<<ggrid, 256, SM_TOTAL>>>(bq, bk, bv, bs, n);
    // launches #5-8: CSR chain (s1)
    degree_kernel<<<(E + 255) / 256, 256, 0, s1>>>(ei, E);
    scan1_kernel<<<nb, SCAN_B, 0, s1>>>(n);
    scan2_kernel<<<1, 128, 0, s1>>>(nb);
    fill_kernel<<<(E + 255) / 256, 256, 0, s1>>>(ei, E);
    cudaEventRecord(evJoin, s1);

    // join: aggregate needs CSR + gemm outputs
    cudaStreamWaitEvent(0, evJoin, 0);
    aggregate_kernel<<<(n * 32 + 255) / 256, 256>>>(out, n);
}

// round 16
// speedup vs baseline: 1.1230x; 1.1230x over previous
#include <cuda_runtime.h>
#include <cuda_bf16.h>
#include <cuda_fp16.h>
#include <cstdint>

#define N_NODES 50000
#define E_EDGES 800000
#define SCAN_B 512

// ---------------- device scratch (static, no allocation) ----------------
__device__ float g_q[N_NODES * 128];
__device__ float g_skip[N_NODES * 32];
__device__ __align__(16) __half g_kvh[N_NODES * 256];  // [node]: k ch0-127, v ch128-255
__device__ int   g_deg[N_NODES];
__device__ int   g_cnt[N_NODES];
__device__ int   g_off[N_NODES];
__device__ int   g_bsum[(N_NODES + SCAN_B - 1) / SCAN_B + 1];
__device__ int   g_srcs[E_EDGES];
// bf16 hi/lo of x (padded to full 128-row tiles; pad stays zero) and W^T per y
__device__ __align__(16) __nv_bfloat16 g_ah[(N_NODES + 128) * 256];
__device__ __align__(16) __nv_bfloat16 g_al[(N_NODES + 128) * 256];
__device__ __align__(16) __nv_bfloat16 g_bh[4 * 128 * 256];
__device__ __align__(16) __nv_bfloat16 g_bl[4 * 128 * 256];

// ---------------- helpers ----------------
__device__ __forceinline__ uint32_t smem_u32(const void* p) {
    uint32_t a;
    asm("{ .reg .u64 t; cvta.to.shared.u64 t, %1; cvt.u32.u64 %0, t; }" : "=r"(a) : "l"(p));
    return a;
}
// SW64 swizzle for 64-byte rows: XOR bits [5:4] with bits [8:7]
#define SWZ64(b) ((b) ^ (((b) >> 3) & 0x30))

__device__ __forceinline__ uint32_t pack_bf16(float a, float b) {
    __nv_bfloat162 h = __floats2bfloat162_rn(a, b);
    return *(uint32_t*)&h;
}

__device__ __forceinline__ void ldsm_x4(uint32_t* r, uint32_t addr) {
    asm volatile("ldmatrix.sync.aligned.m8n8.x4.shared.b16 {%0,%1,%2,%3}, [%4];"
                 : "=r"(r[0]), "=r"(r[1]), "=r"(r[2]), "=r"(r[3]) : "r"(addr));
}

__device__ __forceinline__ void mma16816(float* d, const uint32_t* a, const uint32_t* b) {
    asm volatile(
        "mma.sync.aligned.m16n8k16.row.col.f32.bf16.bf16.f32 "
        "{%0,%1,%2,%3}, {%4,%5,%6,%7}, {%8,%9}, {%0,%1,%2,%3};"
        : "+f"(d[0]), "+f"(d[1]), "+f"(d[2]), "+f"(d[3])
        : "r"(a[0]), "r"(a[1]), "r"(a[2]), "r"(a[3]), "r"(b[0]), "r"(b[1]));
}

// ---------------- conversion kernels ----------------
__global__ void convA_kernel(const float* __restrict__ x, int total4) {
    int i = blockIdx.x * blockDim.x + threadIdx.x;
    if (i >= total4) return;
    float4 v = ((const float4*)x)[i];
    float h0 = __bfloat162float(__float2bfloat16(v.x));
    float h1 = __bfloat162float(__float2bfloat16(v.y));
    float h2 = __bfloat162float(__float2bfloat16(v.z));
    float h3 = __bfloat162float(__float2bfloat16(v.w));
    ((uint2*)g_ah)[i] = make_uint2(pack_bf16(v.x, v.y), pack_bf16(v.z, v.w));
    ((uint2*)g_al)[i] = make_uint2(pack_bf16(v.x - h0, v.y - h1), pack_bf16(v.z - h2, v.w - h3));
}

__global__ void convW_kernel(
    const float* __restrict__ Wq, const float* __restrict__ Wk,
    const float* __restrict__ Wv, const float* __restrict__ Ws)
{
    int y = blockIdx.y;
    const float* W = (y == 0) ? Wq : (y == 1) ? Wk : (y == 2) ? Wv : Ws;
    int N = (y == 3) ? 32 : 128;
    int idx = blockIdx.x * blockDim.x + threadIdx.x;
    if (idx >= 256 * N) return;
    int k = idx / N, nn = idx % N;
    float w = W[idx];
    float h = __bfloat162float(__float2bfloat16(w));
    size_t o = (size_t)y * 32768 + (size_t)nn * 256 + k;  // transposed [n][k]
    g_bh[o] = __float2bfloat16(w);
    g_bl[o] = __float2bfloat16(w - h);
}

// ---------------- init / CSR build ----------------
__global__ void init_kernel(int n) {
    int i = blockIdx.x * blockDim.x + threadIdx.x;
    if (i < n) { g_deg[i] = 0; g_cnt[i] = 0; }
}
__global__ void degree_kernel(const int* __restrict__ ei, int E) {
    int i = blockIdx.x * blockDim.x + threadIdx.x;
    if (i < E) atomicAdd(&g_deg[ei[(size_t)E + i]], 1);
}
__global__ void scan1_kernel(int n) {
    __shared__ int sm[SCAN_B];
    int i = blockIdx.x * SCAN_B + threadIdx.x;
    int v = (i < n) ? g_deg[i] : 0;
    sm[threadIdx.x] = v;
    __syncthreads();
#pragma unroll
    for (int ofs = 1; ofs < SCAN_B; ofs <<= 1) {
        int t = (threadIdx.x >= ofs) ? sm[threadIdx.x - ofs] : 0;
        __syncthreads();
        sm[threadIdx.x] += t;
        __syncthreads();
    }
    if (i < n) g_off[i] = sm[threadIdx.x] - v;
    if (threadIdx.x == SCAN_B - 1) g_bsum[blockIdx.x] = sm[SCAN_B - 1];
}
__global__ void scan2_kernel(int nb) {
    __shared__ int sm[128];
    int v = ((int)threadIdx.x < nb) ? g_bsum[threadIdx.x] : 0;
    sm[threadIdx.x] = v;
    __syncthreads();
#pragma unroll
    for (int ofs = 1; ofs < 128; ofs <<= 1) {
        int t = (threadIdx.x >= ofs) ? sm[threadIdx.x - ofs] : 0;
        __syncthreads();
        sm[threadIdx.x] += t;
        __syncthreads();
    }
    if ((int)threadIdx.x < nb) g_bsum[threadIdx.x] = sm[threadIdx.x] - v;
}
__global__ void fill_kernel(const int* __restrict__ ei, int E) {
    int i = blockIdx.x * blockDim.x + threadIdx.x;
    if (i >= E) return;
    int src = ei[i];
    int dst = ei[(size_t)E + i];
    int pos = g_off[dst] + g_bsum[dst / SCAN_B] + atomicAdd(&g_cnt[dst], 1);
    g_srcs[pos] = src;
}

// ---------------- fused mma.sync GEMM: K-chunks of 32, 32KB smem -------------
// q (y=0), skip (y=3): 3 passes (AhBh + AlBh + AhBl), per-pass ldsm (R14 style,
// keeps regs ~128 / occupancy high — R15 showed hoisting frags loses).
// k (y=1), v (y=2): 1 pass (AhBh); rel_err measured 5.75e-4 < 1e-3.
#define SM_AH   0
#define SM_AL   8192
#define SM_BH   16384
#define SM_BL   24576
#define SM_TOTAL 32768

__global__ void __launch_bounds__(256) gemm_mma_kernel(
    const float* __restrict__ bq, const float* __restrict__ bk,
    const float* __restrict__ bv, const float* __restrict__ bs,
    int M)
{
    extern __shared__ char smem[];
    uint32_t sb = smem_u32(smem);
    int t = threadIdx.x;
    int wid = t >> 5, lane = t & 31;
    int y = blockIdx.y;

    const float* bias = (y == 0) ? bq : (y == 1) ? bk : (y == 2) ? bv : bs;
    float* C = (y == 0) ? g_q : g_skip;  // y=1,2 write g_kvh (half)
    int N = (y == 3) ? 32 : 128;
    int npass = (y == 1 || y == 2) ? 1 : 3;

    const __nv_bfloat16* Bh = g_bh + (size_t)y * 32768;
    const __nv_bfloat16* Bl = g_bl + (size_t)y * 32768;

    int wr = wid >> 1;
    int wc = wid & 1;
    int rowBase = blockIdx.x * 128;

    int npairs = (N - wc * 64) / 16;
    if (npairs < 0) npairs = 0;
    if (npairs > 4) npairs = 4;

    float acc[2][8][4];
#pragma unroll
    for (int i = 0; i < 2; i++)
#pragma unroll
        for (int j = 0; j < 8; j++)
#pragma unroll
            for (int q = 0; q < 4; q++) acc[i][j][q] = 0.0f;

    int a_row = lane & 15;
    int a_k   = (lane >> 4) * 8;
    int b_n   = ((lane >> 4) << 3) + (lane & 7);
    int b_k   = lane & 8;

    for (int c = 0; c < 8; c++) {
        // tile fill: 8KB per matrix = 512 16B segs; 2 segs/thread/matrix.
#pragma unroll
        for (int jj = 0; jj < 2; jj++) {
            int id = t * 2 + jj;           // 0..511
            int row = id >> 2;             // 0..127
            int seg = id & 3;              // 16B segment within 64B row
            uint32_t so = SWZ64((uint32_t)(row * 64 + seg * 16));
            size_t ga = (size_t)(rowBase + row) * 256 + c * 32 + seg * 8;
            size_t gb = (size_t)row * 256 + c * 32 + seg * 8;
            *(uint4*)(smem + SM_AH + so) = *(const uint4*)(g_ah + ga);
            *(uint4*)(smem + SM_BH + so) = *(const uint4*)(Bh + gb);
            if (npass == 3) {
                *(uint4*)(smem + SM_AL + so) = *(const uint4*)(g_al + ga);
                *(uint4*)(smem + SM_BL + so) = *(const uint4*)(Bl + gb);
            }
        }
        __syncthreads();

        for (int pass = 0; pass < npass; pass++) {
            uint32_t Abase = sb + ((pass == 1) ? SM_AL : SM_AH);
            uint32_t Bbase = sb + ((pass == 2) ? SM_BL : SM_BH);
#pragma unroll
            for (int ks = 0; ks < 2; ks++) {
                int k0 = ks * 16;
                uint32_t afrag[2][4];
#pragma unroll
                for (int mt = 0; mt < 2; mt++) {
                    int rr = wr * 32 + mt * 16 + a_row;
                    ldsm_x4(afrag[mt], Abase + SWZ64((uint32_t)(rr * 64 + (k0 + a_k) * 2)));
                }
                uint32_t bfrag[4][4];
                for (int j = 0; j < npairs; j++) {
                    int nn = wc * 64 + j * 16 + b_n;
                    ldsm_x4(bfrag[j], Bbase + SWZ64((uint32_t)(nn * 64 + (k0 + b_k) * 2)));
                }
#pragma unroll
                for (int mt = 0; mt < 2; mt++) {
                    for (int j = 0; j < npairs; j++) {
                        mma16816(acc[mt][2 * j + 0], afrag[mt], &bfrag[j][0]);
                        mma16816(acc[mt][2 * j + 1], afrag[mt], &bfrag[j][2]);
                    }
                }
            }
        }
        __syncthreads();
    }

    // epilogue: q/skip -> fp32, k/v -> half into g_kvh
#pragma unroll
    for (int mt = 0; mt < 2; mt++) {
        for (int nt = 0; nt < npairs * 2; nt++) {
            int col = wc * 64 + nt * 8 + 2 * (lane & 3);
            int rr0 = rowBase + wr * 32 + mt * 16 + (lane >> 2);
            int rr1 = rr0 + 8;
            float bx = bias[col], by = bias[col + 1];
            float o00 = acc[mt][nt][0] + bx, o01 = acc[mt][nt][1] + by;
            float o10 = acc[mt][nt][2] + bx, o11 = acc[mt][nt][3] + by;
            if (npass == 3) {
                if (rr0 < M) *(float2*)&C[(size_t)rr0 * N + col] = make_float2(o00, o01);
                if (rr1 < M) *(float2*)&C[(size_t)rr1 * N + col] = make_float2(o10, o11);
            } else {
                int off = (y == 1) ? 0 : 128;
                if (rr0 < M) *(__half2*)&g_kvh[(size_t)rr0 * 256 + off + col] = __floats2half2_rn(o00, o01);
                if (rr1 < M) *(__half2*)&g_kvh[(size_t)rr1 * 256 + off + col] = __floats2half2_rn(o10, o11);
            }
        }
    }
}

// ---------------- fused aggregation: warp per dst, 2-edge ILP (R9/R11 best) -
__global__ void __launch_bounds__(256) aggregate_kernel(float* __restrict__ out, int n) {
    int w = (int)((blockIdx.x * 256u + threadIdx.x) >> 5);
    if (w >= n) return;
    int lane = threadIdx.x & 31;

    int start = g_off[w] + g_bsum[w / SCAN_B];
    int deg = g_deg[w];
    int end = start + deg;

    float4 q4 = *(const float4*)(g_q + (size_t)w * 128 + lane * 4);
    float4 num = make_float4(0.f, 0.f, 0.f, 0.f);
    float den = 0.0f;
    const float scale = 0.17677669529663687f;  // 1/sqrt(32)

    for (int base = start; base < end; base += 32) {
        int m = end - base;
        int cntc = (m < 32) ? m : 32;
        int my = (lane < cntc) ? g_srcs[base + lane] : 0;
        int i = 0;
        for (; i + 2 <= cntc; i += 2) {
            int s0 = __shfl_sync(0xffffffffu, my, i);
            int s1 = __shfl_sync(0xffffffffu, my, i + 1);
            uint2 kr0 = *(const uint2*)(g_kvh + (size_t)s0 * 256 + lane * 4);
            uint2 kr1 = *(const uint2*)(g_kvh + (size_t)s1 * 256 + lane * 4);
            uint2 vr0 = *(const uint2*)(g_kvh + (size_t)s0 * 256 + 128 + lane * 4);
            uint2 vr1 = *(const uint2*)(g_kvh + (size_t)s1 * 256 + 128 + lane * 4);
            float2 k0a = __half22float2(*(__half2*)&kr0.x), k0b = __half22float2(*(__half2*)&kr0.y);
            float2 k1a = __half22float2(*(__half2*)&kr1.x), k1b = __half22float2(*(__half2*)&kr1.y);
            float p0 = q4.x * k0a.x + q4.y * k0a.y + q4.z * k0b.x + q4.w * k0b.y;
            float p1 = q4.x * k1a.x + q4.y * k1a.y + q4.z * k1b.x + q4.w * k1b.y;
            p0 += __shfl_xor_sync(0xffffffffu, p0, 1);
            p1 += __shfl_xor_sync(0xffffffffu, p1, 1);
            p0 += __shfl_xor_sync(0xffffffffu, p0, 2);
            p1 += __shfl_xor_sync(0xffffffffu, p1, 2);
            p0 += __shfl_xor_sync(0xffffffffu, p0, 4);
            p1 += __shfl_xor_sync(0xffffffffu, p1, 4);
            float e0 = __expf(p0 * scale);
            float e1 = __expf(p1 * scale);
            den += e0 + e1;
            float2 v0a = __half22float2(*(__half2*)&vr0.x), v0b = __half22float2(*(__half2*)&vr0.y);
            float2 v1a = __half22float2(*(__half2*)&vr1.x), v1b = __half22float2(*(__half2*)&vr1.y);
            num.x = fmaf(e0, v0a.x, fmaf(e1, v1a.x, num.x));
            num.y = fmaf(e0, v0a.y, fmaf(e1, v1a.y, num.y));
            num.z = fmaf(e0, v0b.x, fmaf(e1, v1b.x, num.z));
            num.w = fmaf(e0, v0b.y, fmaf(e1, v1b.y, num.w));
        }
        if (i < cntc) {
            int s0 = __shfl_sync(0xffffffffu, my, i);
            uint2 kr0 = *(const uint2*)(g_kvh + (size_t)s0 * 256 + lane * 4);
            uint2 vr0 = *(const uint2*)(g_kvh + (size_t)s0 * 256 + 128 + lane * 4);
            float2 k0a = __half22float2(*(__half2*)&kr0.x), k0b = __half22float2(*(__half2*)&kr0.y);
            float p0 = q4.x * k0a.x + q4.y * k0a.y + q4.z * k0b.x + q4.w * k0b.y;
            p0 += __shfl_xor_sync(0xffffffffu, p0, 1);
            p0 += __shfl_xor_sync(0xffffffffu, p0, 2);
            p0 += __shfl_xor_sync(0xffffffffu, p0, 4);
            float e0 = __expf(p0 * scale);
            den += e0;
            float2 v0a = __half22float2(*(__half2*)&vr0.x), v0b = __half22float2(*(__half2*)&vr0.y);
            num.x = fmaf(e0, v0a.x, num.x);
            num.y = fmaf(e0, v0a.y, num.y);
            num.z = fmaf(e0, v0b.x, num.z);
            num.w = fmaf(e0, v0b.y, num.w);
        }
    }

    float inv = (deg > 0) ? (1.0f / den) : 0.0f;
    num.x *= inv; num.y *= inv; num.z *= inv; num.w *= inv;

#pragma unroll
    for (int ofs = 8; ofs <= 16; ofs <<= 1) {
        num.x += __shfl_xor_sync(0xffffffffu, num.x, ofs);
        num.y += __shfl_xor_sync(0xffffffffu, num.y, ofs);
        num.z += __shfl_xor_sync(0xffffffffu, num.z, ofs);
        num.w += __shfl_xor_sync(0xffffffffu, num.w, ofs);
    }

    if (lane < 8) {
        float4 sk = *(const float4*)(g_skip + (size_t)w * 32 + lane * 4);
        float4 o;
        o.x = 0.25f * num.x + sk.x;
        o.y = 0.25f * num.y + sk.y;
        o.z = 0.25f * num.z + sk.z;
        o.w = 0.25f * num.w + sk.w;
        o.x = (o.x > 0.f) ? o.x : 0.1f * o.x;
        o.y = (o.y > 0.f) ? o.y : 0.1f * o.y;
        o.z = (o.z > 0.f) ? o.z : 0.1f * o.z;
        o.w = (o.w > 0.f) ? o.w : 0.1f * o.w;
        *(float4*)(out + (size_t)w * 32 + lane * 4) = o;
    }
}

// ---------------- launch ----------------
// Submission order puts the fused GEMM at slot #4 (ncu profiles launch #4).
extern "C" void kernel_launch(void* const* d_in, const int* in_sizes, int n_in,
                              void* d_out, int out_size) {
    const float* x  = (const float*)d_in[0];
    const int*   ei = (const int*)d_in[1];
    const float* Wq = (const float*)d_in[2];
    const float* bq = (const float*)d_in[3];
    const float* Wk = (const float*)d_in[4];
    const float* bk = (const float*)d_in[5];
    const float* Wv = (const float*)d_in[6];
    const float* bv = (const float*)d_in[7];
    const float* Ws = (const float*)d_in[8];
    const float* bs = (const float*)d_in[9];
    float* out = (float*)d_out;

    int n = in_sizes[0] / 256;   // 50000
    int E = in_sizes[1] / 2;     // 800000
    int nb = (n + SCAN_B - 1) / SCAN_B;

    static cudaStream_t s1 = nullptr;
    static cudaEvent_t evFork = nullptr, evJoin = nullptr;
    if (s1 == nullptr) {
        cudaStreamCreateWithFlags(&s1, cudaStreamNonBlocking);
        cudaEventCreateWithFlags(&evFork, cudaEventDisableTiming);
        cudaEventCreateWithFlags(&evJoin, cudaEventDisableTiming);
        cudaFuncSetAttribute(gemm_mma_kernel,
                             cudaFuncAttributeMaxDynamicSharedMemorySize, SM_TOTAL);
    }

    // fork for s1 (events are not launches)
    cudaEventRecord(evFork, 0);
    cudaStreamWaitEvent(s1, evFork, 0);

    // launches #1-2: conversions (main)
    convA_kernel<<<(n * 64 + 255) / 256, 256>>>(x, n * 64);
    {
        dim3 wgrid((256 * 128 + 255) / 256, 4);
        convW_kernel<<<wgrid, 256>>>(Wq, Wk, Wv, Ws);
    }
    // launch #3: CSR init (s1)
    init_kernel<<<(n + 255) / 256, 256, 0, s1>>>(n);
    // launch #4: fused GEMM (main) <- ncu window
    dim3 ggrid((n + 127) / 128, 4);
    gemm_mma_kernel<<<ggrid, 256, SM_TOTAL>>>(bq, bk, bv, bs, n);
    // launches #5-8: CSR chain (s1)
    degree_kernel<<<(E + 255) / 256, 256, 0, s1>>>(ei, E);
    scan1_kernel<<<nb, SCAN_B, 0, s1>>>(n);
    scan2_kernel<<<1, 128, 0, s1>>>(nb);
    fill_kernel<<<(E + 255) / 256, 256, 0, s1>>>(ei, E);
    cudaEventRecord(evJoin, s1);

    // join: aggregate needs CSR + gemm outputs
    cudaStreamWaitEvent(0, evJoin, 0);
    aggregate_kernel<<<(n * 32 + 255) / 256, 256>>>(out, n);
}

// round 17
// speedup vs baseline: 1.3349x; 1.1887x over previous
#include <cuda_runtime.h>
#include <cuda_bf16.h>
#include <cuda_fp16.h>
#include <cstdint>

#define N_NODES 50000
#define E_EDGES 800000
#define SCAN_B 512

// ---------------- device scratch (static, no allocation) ----------------
__device__ float g_q[N_NODES * 128];
__device__ float g_skip[N_NODES * 32];
__device__ __align__(16) __half g_kvh[N_NODES * 256];  // [node]: k ch0-127, v ch128-255
__device__ int   g_deg[N_NODES];
__device__ int   g_cnt[N_NODES];
__device__ int   g_off[N_NODES];
__device__ int   g_bsum[(N_NODES + SCAN_B - 1) / SCAN_B + 1];
__device__ int   g_srcs[E_EDGES];
// bf16 hi/lo of x (padded to full 128-row tiles; pad stays zero) and W^T per y
__device__ __align__(16) __nv_bfloat16 g_ah[(N_NODES + 128) * 256];
__device__ __align__(16) __nv_bfloat16 g_al[(N_NODES + 128) * 256];
__device__ __align__(16) __nv_bfloat16 g_bh[4 * 128 * 256];
__device__ __align__(16) __nv_bfloat16 g_bl[4 * 128 * 256];

// ---------------- helpers ----------------
__device__ __forceinline__ uint32_t smem_u32(const void* p) {
    uint32_t a;
    asm("{ .reg .u64 t; cvta.to.shared.u64 t, %1; cvt.u32.u64 %0, t; }" : "=r"(a) : "l"(p));
    return a;
}
// SW64 swizzle for 64-byte rows: XOR bits [5:4] with bits [8:7]
#define SWZ64(b) ((b) ^ (((b) >> 3) & 0x30))

__device__ __forceinline__ uint32_t pack_bf16(float a, float b) {
    __nv_bfloat162 h = __floats2bfloat162_rn(a, b);
    return *(uint32_t*)&h;
}

__device__ __forceinline__ void ldsm_x4(uint32_t* r, uint32_t addr) {
    asm volatile("ldmatrix.sync.aligned.m8n8.x4.shared.b16 {%0,%1,%2,%3}, [%4];"
                 : "=r"(r[0]), "=r"(r[1]), "=r"(r[2]), "=r"(r[3]) : "r"(addr));
}

__device__ __forceinline__ void mma16816(float* d, const uint32_t* a, const uint32_t* b) {
    asm volatile(
        "mma.sync.aligned.m16n8k16.row.col.f32.bf16.bf16.f32 "
        "{%0,%1,%2,%3}, {%4,%5,%6,%7}, {%8,%9}, {%0,%1,%2,%3};"
        : "+f"(d[0]), "+f"(d[1]), "+f"(d[2]), "+f"(d[3])
        : "r"(a[0]), "r"(a[1]), "r"(a[2]), "r"(a[3]), "r"(b[0]), "r"(b[1]));
}

__device__ __forceinline__ void cp16(uint32_t saddr, const void* gptr) {
    asm volatile("cp.async.ca.shared.global [%0], [%1], 16;"
                 :: "r"(saddr), "l"(gptr) : "memory");
}
#define CP_COMMIT() asm volatile("cp.async.commit_group;" ::: "memory")
#define CP_WAIT0()  asm volatile("cp.async.wait_group 0;" ::: "memory")

// ---------------- conversion kernels ----------------
__global__ void convA_kernel(const float* __restrict__ x, int total4) {
    int i = blockIdx.x * blockDim.x + threadIdx.x;
    if (i >= total4) return;
    float4 v = ((const float4*)x)[i];
    float h0 = __bfloat162float(__float2bfloat16(v.x));
    float h1 = __bfloat162float(__float2bfloat16(v.y));
    float h2 = __bfloat162float(__float2bfloat16(v.z));
    float h3 = __bfloat162float(__float2bfloat16(v.w));
    ((uint2*)g_ah)[i] = make_uint2(pack_bf16(v.x, v.y), pack_bf16(v.z, v.w));
    ((uint2*)g_al)[i] = make_uint2(pack_bf16(v.x - h0, v.y - h1), pack_bf16(v.z - h2, v.w - h3));
}

__global__ void convW_kernel(
    const float* __restrict__ Wq, const float* __restrict__ Wk,
    const float* __restrict__ Wv, const float* __restrict__ Ws)
{
    int y = blockIdx.y;
    const float* W = (y == 0) ? Wq : (y == 1) ? Wk : (y == 2) ? Wv : Ws;
    int N = (y == 3) ? 32 : 128;
    int idx = blockIdx.x * blockDim.x + threadIdx.x;
    if (idx >= 256 * N) return;
    int k = idx / N, nn = idx % N;
    float w = W[idx];
    float h = __bfloat162float(__float2bfloat16(w));
    size_t o = (size_t)y * 32768 + (size_t)nn * 256 + k;  // transposed [n][k]
    g_bh[o] = __float2bfloat16(w);
    g_bl[o] = __float2bfloat16(w - h);
}

// ---------------- init / CSR build ----------------
__global__ void init_kernel(int n) {
    int i = blockIdx.x * blockDim.x + threadIdx.x;
    if (i < n) { g_deg[i] = 0; g_cnt[i] = 0; }
}
__global__ void degree_kernel(const int* __restrict__ ei, int E) {
    int i = blockIdx.x * blockDim.x + threadIdx.x;
    if (i < E) atomicAdd(&g_deg[ei[(size_t)E + i]], 1);
}
__global__ void scan1_kernel(int n) {
    __shared__ int sm[SCAN_B];
    int i = blockIdx.x * SCAN_B + threadIdx.x;
    int v = (i < n) ? g_deg[i] : 0;
    sm[threadIdx.x] = v;
    __syncthreads();
#pragma unroll
    for (int ofs = 1; ofs < SCAN_B; ofs <<= 1) {
        int t = (threadIdx.x >= ofs) ? sm[threadIdx.x - ofs] : 0;
        __syncthreads();
        sm[threadIdx.x] += t;
        __syncthreads();
    }
    if (i < n) g_off[i] = sm[threadIdx.x] - v;
    if (threadIdx.x == SCAN_B - 1) g_bsum[blockIdx.x] = sm[SCAN_B - 1];
}
__global__ void scan2_kernel(int nb) {
    __shared__ int sm[128];
    int v = ((int)threadIdx.x < nb) ? g_bsum[threadIdx.x] : 0;
    sm[threadIdx.x] = v;
    __syncthreads();
#pragma unroll
    for (int ofs = 1; ofs < 128; ofs <<= 1) {
        int t = (threadIdx.x >= ofs) ? sm[threadIdx.x - ofs] : 0;
        __syncthreads();
        sm[threadIdx.x] += t;
        __syncthreads();
    }
    if ((int)threadIdx.x < nb) g_bsum[threadIdx.x] = sm[threadIdx.x] - v;
}
__global__ void fill_kernel(const int* __restrict__ ei, int E) {
    int i = blockIdx.x * blockDim.x + threadIdx.x;
    if (i >= E) return;
    int src = ei[i];
    int dst = ei[(size_t)E + i];
    int pos = g_off[dst] + g_bsum[dst / SCAN_B] + atomicAdd(&g_cnt[dst], 1);
    g_srcs[pos] = src;
}

// ---------------- fused mma.sync GEMM: K-chunks of 32, 32KB smem -------------
// q (y=0): 2 passes (AhBh + AlBh).  skip (y=3): 3 passes (+ AhBl).
// k (y=1), v (y=2): 1 pass (AhBh).
// Fills via cp.async (no reg staging); ldsm offsets hoisted out of chunk loop.
#define SM_AH   0
#define SM_AL   8192
#define SM_BH   16384
#define SM_BL   24576
#define SM_TOTAL 32768

__global__ void __launch_bounds__(256) gemm_mma_kernel(
    const float* __restrict__ bq, const float* __restrict__ bk,
    const float* __restrict__ bv, const float* __restrict__ bs,
    int M)
{
    extern __shared__ char smem[];
    uint32_t sb = smem_u32(smem);
    int t = threadIdx.x;
    int wid = t >> 5, lane = t & 31;
    int y = blockIdx.y;

    const float* bias = (y == 0) ? bq : (y == 1) ? bk : (y == 2) ? bv : bs;
    float* C = (y == 0) ? g_q : g_skip;  // y=1,2 write g_kvh (half)
    int N = (y == 3) ? 32 : 128;
    int npass = (y == 0) ? 2 : (y == 3) ? 3 : 1;

    const __nv_bfloat16* Bh = g_bh + (size_t)y * 32768;
    const __nv_bfloat16* Bl = g_bl + (size_t)y * 32768;

    int wr = wid >> 1;
    int wc = wid & 1;
    int rowBase = blockIdx.x * 128;

    int npairs = (N - wc * 64) / 16;
    if (npairs < 0) npairs = 0;
    if (npairs > 4) npairs = 4;

    float acc[2][8][4];
#pragma unroll
    for (int i = 0; i < 2; i++)
#pragma unroll
        for (int j = 0; j < 8; j++)
#pragma unroll
            for (int q = 0; q < 4; q++) acc[i][j][q] = 0.0f;

    int a_row = lane & 15;
    int a_k   = (lane >> 4) * 8;
    int b_n   = ((lane >> 4) << 3) + (lane & 7);
    int b_k   = lane & 8;

    // hoisted ldsm offsets (chunk/pass invariant)
    uint32_t aoff[2][2], boff[4][2];
#pragma unroll
    for (int ks = 0; ks < 2; ks++) {
#pragma unroll
        for (int mt = 0; mt < 2; mt++) {
            int rr = wr * 32 + mt * 16 + a_row;
            aoff[mt][ks] = SWZ64((uint32_t)(rr * 64 + (ks * 16 + a_k) * 2));
        }
#pragma unroll
        for (int j = 0; j < 4; j++) {
            int nn = wc * 64 + j * 16 + b_n;
            boff[j][ks] = SWZ64((uint32_t)(nn * 64 + (ks * 16 + b_k) * 2));
        }
    }

    // hoisted fill addresses
    int fid0 = t * 2, fid1 = t * 2 + 1;
    uint32_t fso0 = SWZ64((uint32_t)((fid0 >> 2) * 64 + (fid0 & 3) * 16));
    uint32_t fso1 = SWZ64((uint32_t)((fid1 >> 2) * 64 + (fid1 & 3) * 16));
    size_t fga0 = (size_t)(rowBase + (fid0 >> 2)) * 256 + (fid0 & 3) * 8;
    size_t fga1 = (size_t)(rowBase + (fid1 >> 2)) * 256 + (fid1 & 3) * 8;
    size_t fgb0 = (size_t)(fid0 >> 2) * 256 + (fid0 & 3) * 8;
    size_t fgb1 = (size_t)(fid1 >> 2) * 256 + (fid1 & 3) * 8;

    for (int c = 0; c < 8; c++) {
        int ko = c * 32;
        cp16(sb + SM_AH + fso0, g_ah + fga0 + ko);
        cp16(sb + SM_AH + fso1, g_ah + fga1 + ko);
        cp16(sb + SM_BH + fso0, Bh + fgb0 + ko);
        cp16(sb + SM_BH + fso1, Bh + fgb1 + ko);
        if (npass >= 2) {
            cp16(sb + SM_AL + fso0, g_al + fga0 + ko);
            cp16(sb + SM_AL + fso1, g_al + fga1 + ko);
        }
        if (npass == 3) {
            cp16(sb + SM_BL + fso0, Bl + fgb0 + ko);
            cp16(sb + SM_BL + fso1, Bl + fgb1 + ko);
        }
        CP_COMMIT();
        CP_WAIT0();
        __syncthreads();

        for (int pass = 0; pass < npass; pass++) {
            uint32_t Abase = sb + ((pass == 1) ? SM_AL : SM_AH);
            uint32_t Bbase = sb + ((pass == 2) ? SM_BL : SM_BH);
#pragma unroll
            for (int ks = 0; ks < 2; ks++) {
                uint32_t afrag[2][4];
#pragma unroll
                for (int mt = 0; mt < 2; mt++)
                    ldsm_x4(afrag[mt], Abase + aoff[mt][ks]);
                uint32_t bfrag[4][4];
                for (int j = 0; j < npairs; j++)
                    ldsm_x4(bfrag[j], Bbase + boff[j][ks]);
#pragma unroll
                for (int mt = 0; mt < 2; mt++) {
                    for (int j = 0; j < npairs; j++) {
                        mma16816(acc[mt][2 * j + 0], afrag[mt], &bfrag[j][0]);
                        mma16816(acc[mt][2 * j + 1], afrag[mt], &bfrag[j][2]);
                    }
                }
            }
        }
        __syncthreads();
    }

    // epilogue: q/skip -> fp32, k/v -> half into g_kvh
#pragma unroll
    for (int mt = 0; mt < 2; mt++) {
        for (int nt = 0; nt < npairs * 2; nt++) {
            int col = wc * 64 + nt * 8 + 2 * (lane & 3);
            int rr0 = rowBase + wr * 32 + mt * 16 + (lane >> 2);
            int rr1 = rr0 + 8;
            float bx = bias[col], by = bias[col + 1];
            float o00 = acc[mt][nt][0] + bx, o01 = acc[mt][nt][1] + by;
            float o10 = acc[mt][nt][2] + bx, o11 = acc[mt][nt][3] + by;
            if (y == 0 || y == 3) {
                if (rr0 < M) *(float2*)&C[(size_t)rr0 * N + col] = make_float2(o00, o01);
                if (rr1 < M) *(float2*)&C[(size_t)rr1 * N + col] = make_float2(o10, o11);
            } else {
                int off = (y == 1) ? 0 : 128;
                if (rr0 < M) *(__half2*)&g_kvh[(size_t)rr0 * 256 + off + col] = __floats2half2_rn(o00, o01);
                if (rr1 < M) *(__half2*)&g_kvh[(size_t)rr1 * 256 + off + col] = __floats2half2_rn(o10, o11);
            }
        }
    }
}

// ---------------- fused aggregation: warp per dst, 2-edge ILP (R9/R11 best) -
__global__ void __launch_bounds__(256) aggregate_kernel(float* __restrict__ out, int n) {
    int w = (int)((blockIdx.x * 256u + threadIdx.x) >> 5);
    if (w >= n) return;
    int lane = threadIdx.x & 31;

    int start = g_off[w] + g_bsum[w / SCAN_B];
    int deg = g_deg[w];
    int end = start + deg;

    float4 q4 = *(const float4*)(g_q + (size_t)w * 128 + lane * 4);
    float4 num = make_float4(0.f, 0.f, 0.f, 0.f);
    float den = 0.0f;
    const float scale = 0.17677669529663687f;  // 1/sqrt(32)

    for (int base = start; base < end; base += 32) {
        int m = end - base;
        int cntc = (m < 32) ? m : 32;
        int my = (lane < cntc) ? g_srcs[base + lane] : 0;
        int i = 0;
        for (; i + 2 <= cntc; i += 2) {
            int s0 = __shfl_sync(0xffffffffu, my, i);
            int s1 = __shfl_sync(0xffffffffu, my, i + 1);
            uint2 kr0 = *(const uint2*)(g_kvh + (size_t)s0 * 256 + lane * 4);
            uint2 kr1 = *(const uint2*)(g_kvh + (size_t)s1 * 256 + lane * 4);
            uint2 vr0 = *(const uint2*)(g_kvh + (size_t)s0 * 256 + 128 + lane * 4);
            uint2 vr1 = *(const uint2*)(g_kvh + (size_t)s1 * 256 + 128 + lane * 4);
            float2 k0a = __half22float2(*(__half2*)&kr0.x), k0b = __half22float2(*(__half2*)&kr0.y);
            float2 k1a = __half22float2(*(__half2*)&kr1.x), k1b = __half22float2(*(__half2*)&kr1.y);
            float p0 = q4.x * k0a.x + q4.y * k0a.y + q4.z * k0b.x + q4.w * k0b.y;
            float p1 = q4.x * k1a.x + q4.y * k1a.y + q4.z * k1b.x + q4.w * k1b.y;
            p0 += __shfl_xor_sync(0xffffffffu, p0, 1);
            p1 += __shfl_xor_sync(0xffffffffu, p1, 1);
            p0 += __shfl_xor_sync(0xffffffffu, p0, 2);
            p1 += __shfl_xor_sync(0xffffffffu, p1, 2);
            p0 += __shfl_xor_sync(0xffffffffu, p0, 4);
            p1 += __shfl_xor_sync(0xffffffffu, p1, 4);
            float e0 = __expf(p0 * scale);
            float e1 = __expf(p1 * scale);
            den += e0 + e1;
            float2 v0a = __half22float2(*(__half2*)&vr0.x), v0b = __half22float2(*(__half2*)&vr0.y);
            float2 v1a = __half22float2(*(__half2*)&vr1.x), v1b = __half22float2(*(__half2*)&vr1.y);
            num.x = fmaf(e0, v0a.x, fmaf(e1, v1a.x, num.x));
            num.y = fmaf(e0, v0a.y, fmaf(e1, v1a.y, num.y));
            num.z = fmaf(e0, v0b.x, fmaf(e1, v1b.x, num.z));
            num.w = fmaf(e0, v0b.y, fmaf(e1, v1b.y, num.w));
        }
        if (i < cntc) {
            int s0 = __shfl_sync(0xffffffffu, my, i);
            uint2 kr0 = *(const uint2*)(g_kvh + (size_t)s0 * 256 + lane * 4);
            uint2 vr0 = *(const uint2*)(g_kvh + (size_t)s0 * 256 + 128 + lane * 4);
            float2 k0a = __half22float2(*(__half2*)&kr0.x), k0b = __half22float2(*(__half2*)&kr0.y);
            float p0 = q4.x * k0a.x + q4.y * k0a.y + q4.z * k0b.x + q4.w * k0b.y;
            p0 += __shfl_xor_sync(0xffffffffu, p0, 1);
            p0 += __shfl_xor_sync(0xffffffffu, p0, 2);
            p0 += __shfl_xor_sync(0xffffffffu, p0, 4);
            float e0 = __expf(p0 * scale);
            den += e0;
            float2 v0a = __half22float2(*(__half2*)&vr0.x), v0b = __half22float2(*(__half2*)&vr0.y);
            num.x = fmaf(e0, v0a.x, num.x);
            num.y = fmaf(e0, v0a.y, num.y);
            num.z = fmaf(e0, v0b.x, num.z);
            num.w = fmaf(e0, v0b.y, num.w);
        }
    }

    float inv = (deg > 0) ? (1.0f / den) : 0.0f;
    num.x *= inv; num.y *= inv; num.z *= inv; num.w *= inv;

#pragma unroll
    for (int ofs = 8; ofs <= 16; ofs <<= 1) {
        num.x += __shfl_xor_sync(0xffffffffu, num.x, ofs);
        num.y += __shfl_xor_sync(0xffffffffu, num.y, ofs);
        num.z += __shfl_xor_sync(0xffffffffu, num.z, ofs);
        num.w += __shfl_xor_sync(0xffffffffu, num.w, ofs);
    }

    if (lane < 8) {
        float4 sk = *(const float4*)(g_skip + (size_t)w * 32 + lane * 4);
        float4 o;
        o.x = 0.25f * num.x + sk.x;
        o.y = 0.25f * num.y + sk.y;
        o.z = 0.25f * num.z + sk.z;
        o.w = 0.25f * num.w + sk.w;
        o.x = (o.x > 0.f) ? o.x : 0.1f * o.x;
        o.y = (o.y > 0.f) ? o.y : 0.1f * o.y;
        o.z = (o.z > 0.f) ? o.z : 0.1f * o.z;
        o.w = (o.w > 0.f) ? o.w : 0.1f * o.w;
        *(float4*)(out + (size_t)w * 32 + lane * 4) = o;
    }
}

// ---------------- launch ----------------
// Submission order puts the fused GEMM at slot #4 (ncu profiles launch #4).
extern "C" void kernel_launch(void* const* d_in, const int* in_sizes, int n_in,
                              void* d_out, int out_size) {
    const float* x  = (const float*)d_in[0];
    const int*   ei = (const int*)d_in[1];
    const float* Wq = (const float*)d_in[2];
    const float* bq = (const float*)d_in[3];
    const float* Wk = (const float*)d_in[4];
    const float* bk = (const float*)d_in[5];
    const float* Wv = (const float*)d_in[6];
    const float* bv = (const float*)d_in[7];
    const float* Ws = (const float*)d_in[8];
    const float* bs = (const float*)d_in[9];
    float* out = (float*)d_out;

    int n = in_sizes[0] / 256;   // 50000
    int E = in_sizes[1] / 2;     // 800000
    int nb = (n + SCAN_B - 1) / SCAN_B;

    static cudaStream_t s1 = nullptr;
    static cudaEvent_t evFork = nullptr, evJoin = nullptr;
    if (s1 == nullptr) {
        cudaStreamCreateWithFlags(&s1, cudaStreamNonBlocking);
        cudaEventCreateWithFlags(&evFork, cudaEventDisableTiming);
        cudaEventCreateWithFlags(&evJoin, cudaEventDisableTiming);
        cudaFuncSetAttribute(gemm_mma_kernel,
                             cudaFuncAttributeMaxDynamicSharedMemorySize, SM_TOTAL);
    }

    // fork for s1 (events are not launches)
    cudaEventRecord(evFork, 0);
    cudaStreamWaitEvent(s1, evFork, 0);

    // launches #1-2: conversions (main)
    convA_kernel<<<(n * 64 + 255) / 256, 256>>>(x, n * 64);
    {
        dim3 wgrid((256 * 128 + 255) / 256, 4);
        convW_kernel<<<wgrid, 256>>>(Wq, Wk, Wv, Ws);
    }
    // launch #3: CSR init (s1)
    init_kernel<<<(n + 255) / 256, 256, 0, s1>>>(n);
    // launch #4: fused GEMM (main) <- ncu window
    dim3 ggrid((n + 127) / 128, 4);
    gemm_mma_kernel<<<ggrid, 256, SM_TOTAL>>>(bq, bk, bv, bs, n);
    // launches #5-8: CSR chain (s1)
    degree_kernel<<<(E + 255) / 256, 256, 0, s1>>>(ei, E);
    scan1_kernel<<<nb, SCAN_B, 0, s1>>>(n);
    scan2_kernel<<<1, 128, 0, s1>>>(nb);
    fill_kernel<<<(E + 255) / 256, 256, 0, s1>>>(ei, E);
    cudaEventRecord(evJoin, s1);

    // join: aggregate needs CSR + gemm outputs
    cudaStreamWaitEvent(0, evJoin, 0);
    aggregate_kernel<<<(n * 32 + 255) / 256, 256>>>(out, n);
}